// round 3
// baseline (speedup 1.0000x reference)
#include <cuda_runtime.h>
#include <cstddef>

#define N_NODES     100000
#define N_EDGES     800000
#define F           128
#define NUM_GRAPHS  128
#define NUM_CLASSES 10
#define BN_EPS      1e-5f

// ---------------- scratch (static device globals; no allocation) ----------------
__device__ float g_bufA[(size_t)N_NODES * F];   // 51.2 MB
__device__ float g_bufB[(size_t)N_NODES * F];   // 51.2 MB
__device__ float g_bufC[(size_t)N_NODES * F];   // 51.2 MB
__device__ float g_sum1[F];
__device__ float g_sq1[F];
__device__ float g_sum2[F];
__device__ float g_sq2[F];
__device__ float g_pooled[NUM_GRAPHS * F];
__device__ float g_counts[NUM_GRAPHS];

// ---------------- zero the small accumulators (must re-zero every replay) ------
__global__ void zero_small_kernel() {
    int t = blockIdx.x * blockDim.x + threadIdx.x;
    if (t < F) {
        g_sum1[t] = 0.f; g_sq1[t] = 0.f;
        g_sum2[t] = 0.f; g_sq2[t] = 0.f;
    }
    if (t < NUM_GRAPHS) g_counts[t] = 0.f;
    for (int i = t; i < NUM_GRAPHS * F; i += blockDim.x * gridDim.x)
        g_pooled[i] = 0.f;
}

// ---------------- copy init: agg = x ------------------------------------------
__global__ void copy_kernel(const float* __restrict__ src, float* __restrict__ dst) {
    size_t i = (size_t)blockIdx.x * blockDim.x + threadIdx.x;
    size_t n4 = (size_t)N_NODES * F / 4;
    const float4* s4 = reinterpret_cast<const float4*>(src);
    float4* d4 = reinterpret_cast<float4*>(dst);
    for (; i < n4; i += (size_t)blockDim.x * gridDim.x)
        d4[i] = s4[i];
}

// ---------------- edge scatter-add: agg[dst] += x[src] -------------------------
// one warp per edge, float4 vector atomics (sm_90+). edge_index is int32.
__global__ void scatter_kernel(const float* __restrict__ X,
                               const int* __restrict__ ei,
                               float* __restrict__ agg) {
    int widx = (int)(((size_t)blockIdx.x * blockDim.x + threadIdx.x) >> 5);
    int lane = threadIdx.x & 31;
    if (widx >= N_EDGES) return;
    int s = ei[widx];
    int d = ei[N_EDGES + widx];
    float4 v = reinterpret_cast<const float4*>(X + (size_t)s * F)[lane];
    atomicAdd(reinterpret_cast<float4*>(agg + (size_t)d * F) + lane, v);
}

// ---------------- GEMM: C[M x 128] = A[M x 128] @ W[128 x 128] + b (opt ReLU) --
// BM=128, BN=128, BK=16, 256 threads, 8x8 register tile per thread.
__global__ void __launch_bounds__(256)
gemm128_kernel(const float* __restrict__ A, const float* __restrict__ W,
               const float* __restrict__ bias, float* __restrict__ C,
               int M, int relu) {
    __shared__ float As[16][128];
    __shared__ float Bs[16][128];
    const int t  = threadIdx.x;
    const int tx = t & 15;       // col tile  (16 x 8 = 128 cols)
    const int ty = t >> 4;       // row tile  (16 x 8 = 128 rows)
    const int rowBase = blockIdx.x * 128;

    const int aRowL   = t >> 1;         // 0..127
    const int aColOff = (t & 1) * 8;    // 0 or 8
    const int bRowL   = t >> 4;         // 0..15
    const int bColOff = (t & 15) * 8;   // 0..120

    float acc[8][8];
#pragma unroll
    for (int i = 0; i < 8; i++)
#pragma unroll
        for (int j = 0; j < 8; j++) acc[i][j] = 0.f;

    const int  aRow   = rowBase + aRowL;
    const bool aValid = (aRow < M);

    for (int kc = 0; kc < 8; kc++) {
        // --- load A tile (128 rows x 16 k), transposed into As[k][m]
        float4 a0 = make_float4(0.f, 0.f, 0.f, 0.f), a1 = a0;
        if (aValid) {
            const float4* p = reinterpret_cast<const float4*>(
                A + (size_t)aRow * 128 + kc * 16 + aColOff);
            a0 = p[0]; a1 = p[1];
        }
        As[aColOff + 0][aRowL] = a0.x;
        As[aColOff + 1][aRowL] = a0.y;
        As[aColOff + 2][aRowL] = a0.z;
        As[aColOff + 3][aRowL] = a0.w;
        As[aColOff + 4][aRowL] = a1.x;
        As[aColOff + 5][aRowL] = a1.y;
        As[aColOff + 6][aRowL] = a1.z;
        As[aColOff + 7][aRowL] = a1.w;

        // --- load B tile (16 k x 128 n), direct
        {
            const float4* q = reinterpret_cast<const float4*>(
                W + (size_t)(kc * 16 + bRowL) * 128 + bColOff);
            *reinterpret_cast<float4*>(&Bs[bRowL][bColOff + 0]) = q[0];
            *reinterpret_cast<float4*>(&Bs[bRowL][bColOff + 4]) = q[1];
        }
        __syncthreads();

#pragma unroll
        for (int k = 0; k < 16; k++) {
            float4 af0 = *reinterpret_cast<const float4*>(&As[k][ty * 8 + 0]);
            float4 af1 = *reinterpret_cast<const float4*>(&As[k][ty * 8 + 4]);
            float4 bf0 = *reinterpret_cast<const float4*>(&Bs[k][tx * 8 + 0]);
            float4 bf1 = *reinterpret_cast<const float4*>(&Bs[k][tx * 8 + 4]);
            float a[8] = {af0.x, af0.y, af0.z, af0.w, af1.x, af1.y, af1.z, af1.w};
            float b[8] = {bf0.x, bf0.y, bf0.z, bf0.w, bf1.x, bf1.y, bf1.z, bf1.w};
#pragma unroll
            for (int r = 0; r < 8; r++)
#pragma unroll
                for (int c = 0; c < 8; c++)
                    acc[r][c] += a[r] * b[c];
        }
        __syncthreads();
    }

    // --- epilogue: bias (+ReLU) + store
#pragma unroll
    for (int r = 0; r < 8; r++) {
        int row = rowBase + ty * 8 + r;
        if (row >= M) continue;
#pragma unroll
        for (int c = 0; c < 8; c += 4) {
            int col = tx * 8 + c;
            float4 v;
            v.x = acc[r][c + 0] + bias[col + 0];
            v.y = acc[r][c + 1] + bias[col + 1];
            v.z = acc[r][c + 2] + bias[col + 2];
            v.w = acc[r][c + 3] + bias[col + 3];
            if (relu) {
                v.x = fmaxf(v.x, 0.f); v.y = fmaxf(v.y, 0.f);
                v.z = fmaxf(v.z, 0.f); v.w = fmaxf(v.w, 0.f);
            }
            *reinterpret_cast<float4*>(C + (size_t)row * 128 + col) = v;
        }
    }
}

// ---------------- BN statistics: per-column sum and sum-of-squares -------------
__global__ void bn_stats_kernel(const float* __restrict__ H,
                                float* __restrict__ sum, float* __restrict__ sq) {
    int c = threadIdx.x;   // blockDim = 128
    float s = 0.f, q = 0.f;
    for (int r = blockIdx.x; r < N_NODES; r += gridDim.x) {
        float v = H[(size_t)r * F + c];
        s += v;
        q += v * v;
    }
    atomicAdd(&sum[c], s);
    atomicAdd(&sq[c], q);
}

// ---------------- BN apply + ReLU, writing TWO outputs (h_norm and agg init) ---
__global__ void bn_apply_dual_kernel(const float* __restrict__ H,
                                     const float* __restrict__ sum,
                                     const float* __restrict__ sq,
                                     const float* __restrict__ gamma,
                                     const float* __restrict__ beta,
                                     float* __restrict__ Hn,
                                     float* __restrict__ Agg) {
    size_t idx0 = (size_t)blockIdx.x * blockDim.x + threadIdx.x;
    int c = (int)(idx0 & 127);   // stride is a multiple of 128 -> col fixed per thread
    const float invN = 1.0f / (float)N_NODES;
    float mean  = sum[c] * invN;
    float var   = fmaxf(sq[c] * invN - mean * mean, 0.f);
    float scale = gamma[c] * rsqrtf(var + BN_EPS);
    float shift = beta[c] - mean * scale;
    size_t total  = (size_t)N_NODES * F;
    size_t stride = (size_t)blockDim.x * gridDim.x;
    for (size_t i = idx0; i < total; i += stride) {
        float v = fmaxf(H[i] * scale + shift, 0.f);
        Hn[i]  = v;
        Agg[i] = v;
    }
}

// ---------------- per-graph node counts (batch is int32) -----------------------
__global__ void count_kernel(const int* __restrict__ batch) {
    int i = blockIdx.x * blockDim.x + threadIdx.x;
    if (i < N_NODES) atomicAdd(&g_counts[batch[i]], 1.0f);
}

// ---------------- fused BN2 + ReLU + segmented pool (batch sorted) -------------
#define POOL_CHUNK 512
__global__ void pool_kernel(const float* __restrict__ H,
                            const float* __restrict__ sum,
                            const float* __restrict__ sq,
                            const float* __restrict__ gamma,
                            const float* __restrict__ beta,
                            const int* __restrict__ batch) {
    const int c = threadIdx.x;   // blockDim = 128
    const float invN = 1.0f / (float)N_NODES;
    float mean  = sum[c] * invN;
    float var   = fmaxf(sq[c] * invN - mean * mean, 0.f);
    float scale = gamma[c] * rsqrtf(var + BN_EPS);
    float shift = beta[c] - mean * scale;

    int r0 = blockIdx.x * POOL_CHUNK;
    if (r0 >= N_NODES) return;
    int r1 = min(r0 + POOL_CHUNK, N_NODES);

    int g = batch[r0];
    float acc = 0.f;
    for (int r = r0; r < r1; r++) {
        int gg = batch[r];
        if (gg != g) {
            atomicAdd(&g_pooled[g * F + c], acc);
            acc = 0.f;
            g = gg;
        }
        float v = fmaxf(H[(size_t)r * F + c] * scale + shift, 0.f);
        acc += v;
    }
    atomicAdd(&g_pooled[g * F + c], acc);
}

// ---------------- head: mean-pool divide + linear + log_softmax ----------------
__global__ void head_kernel(const float* __restrict__ Wlin,
                            const float* __restrict__ blin,
                            float* __restrict__ out) {
    __shared__ float Ws[F * NUM_CLASSES];
    int t = threadIdx.x;   // blockDim = 128, one thread per graph
    for (int i = t; i < F * NUM_CLASSES; i += 128) Ws[i] = Wlin[i];
    __syncthreads();

    int g = t;
    float inv = 1.0f / fmaxf(g_counts[g], 1.0f);
    float logit[NUM_CLASSES];
#pragma unroll
    for (int j = 0; j < NUM_CLASSES; j++) logit[j] = blin[j];
    for (int c = 0; c < F; c++) {
        float p = g_pooled[g * F + c] * inv;
#pragma unroll
        for (int j = 0; j < NUM_CLASSES; j++)
            logit[j] += p * Ws[c * NUM_CLASSES + j];
    }
    float m = logit[0];
#pragma unroll
    for (int j = 1; j < NUM_CLASSES; j++) m = fmaxf(m, logit[j]);
    float se = 0.f;
#pragma unroll
    for (int j = 0; j < NUM_CLASSES; j++) se += expf(logit[j] - m);
    float lse = logf(se);
#pragma unroll
    for (int j = 0; j < NUM_CLASSES; j++)
        out[g * NUM_CLASSES + j] = logit[j] - m - lse;
}

// ================================================================================
extern "C" void kernel_launch(void* const* d_in, const int* in_sizes, int n_in,
                              void* d_out, int out_size) {
    const float* x     = (const float*)d_in[0];
    const int*   ei    = (const int*)d_in[1];     // int32 (harness downcasts int64)
    const int*   batch = (const int*)d_in[2];     // int32
    const float* W1a = (const float*)d_in[3];
    const float* b1a = (const float*)d_in[4];
    const float* W1b = (const float*)d_in[5];
    const float* b1b = (const float*)d_in[6];
    const float* gamma1 = (const float*)d_in[7];
    const float* beta1  = (const float*)d_in[8];
    const float* W2a = (const float*)d_in[9];
    const float* b2a = (const float*)d_in[10];
    const float* W2b = (const float*)d_in[11];
    const float* b2b = (const float*)d_in[12];
    const float* gamma2 = (const float*)d_in[13];
    const float* beta2  = (const float*)d_in[14];
    const float* Wlin = (const float*)d_in[15];
    const float* blin = (const float*)d_in[16];
    float* out = (float*)d_out;

    float *pA, *pB, *pC, *pSum1, *pSq1, *pSum2, *pSq2;
    cudaGetSymbolAddress((void**)&pA, g_bufA);
    cudaGetSymbolAddress((void**)&pB, g_bufB);
    cudaGetSymbolAddress((void**)&pC, g_bufC);
    cudaGetSymbolAddress((void**)&pSum1, g_sum1);
    cudaGetSymbolAddress((void**)&pSq1,  g_sq1);
    cudaGetSymbolAddress((void**)&pSum2, g_sum2);
    cudaGetSymbolAddress((void**)&pSq2,  g_sq2);

    const int M = N_NODES;
    const int gemmBlocks = (M + 127) / 128;
    const int scatterBlocks = (N_EDGES * 32) / 256;  // warp per edge, 256 thr/blk

    // zero small accumulators
    zero_small_kernel<<<64, 256>>>();

    // ---- layer 1: agg1 = x + scatter(x) -> bufA
    copy_kernel<<<4096, 256>>>(x, pA);
    scatter_kernel<<<scatterBlocks, 256>>>(x, ei, pA);
    // MLP1: t1 = relu(agg1 @ W1a + b1a) -> bufB ; h1 = t1 @ W1b + b1b -> bufA
    gemm128_kernel<<<gemmBlocks, 256>>>(pA, W1a, b1a, pB, M, 1);
    gemm128_kernel<<<gemmBlocks, 256>>>(pB, W1b, b1b, pA, M, 0);
    // BN1 stats on bufA
    bn_stats_kernel<<<1024, 128>>>(pA, pSum1, pSq1);
    // h1n = relu(bn(h1)) -> bufB,  agg2 init = h1n -> bufC
    bn_apply_dual_kernel<<<4096, 256>>>(pA, pSum1, pSq1, gamma1, beta1, pB, pC);

    // ---- layer 2: agg2 = h1n + scatter(h1n) -> bufC
    scatter_kernel<<<scatterBlocks, 256>>>(pB, ei, pC);
    // MLP2: t2 = relu(agg2 @ W2a + b2a) -> bufA ; h2 = t2 @ W2b + b2b -> bufB
    gemm128_kernel<<<gemmBlocks, 256>>>(pC, W2a, b2a, pA, M, 1);
    gemm128_kernel<<<gemmBlocks, 256>>>(pA, W2b, b2b, pB, M, 0);
    // BN2 stats on bufB
    bn_stats_kernel<<<1024, 128>>>(pB, pSum2, pSq2);

    // ---- pooling + head
    count_kernel<<<(N_NODES + 255) / 256, 256>>>(batch);
    pool_kernel<<<(N_NODES + POOL_CHUNK - 1) / POOL_CHUNK, 128>>>(
        pB, pSum2, pSq2, gamma2, beta2, batch);
    head_kernel<<<1, 128>>>(Wlin, blin, out);
}

// round 4
// speedup vs baseline: 1.3219x; 1.3219x over previous
#include <cuda_runtime.h>
#include <cuda_bf16.h>
#include <cstdint>
#include <cstddef>

#define N_NODES     100000
#define N_EDGES     800000
#define F           128
#define NUM_GRAPHS  128
#define NUM_CLASSES 10
#define BN_EPS      1e-5f

// ---------------- scratch (static device globals; no allocation) ----------------
__device__ float g_bufA[(size_t)N_NODES * F];   // 51.2 MB
__device__ float g_bufB[(size_t)N_NODES * F];   // 51.2 MB
__device__ float g_bufC[(size_t)N_NODES * F];   // 51.2 MB
__device__ float g_sum1[F];
__device__ float g_sq1[F];
__device__ float g_sum2[F];
__device__ float g_sq2[F];
__device__ float g_pooled[NUM_GRAPHS * F];
__device__ float g_counts[NUM_GRAPHS];
// pre-packed bf16 mma B-fragments for the 4 weight matrices (hi and lo split)
__device__ uint32_t g_wtabH[4][8192];
__device__ uint32_t g_wtabL[4][8192];

// ---------------- zero the small accumulators (must re-zero every replay) ------
__global__ void zero_small_kernel() {
    int t = blockIdx.x * blockDim.x + threadIdx.x;
    if (t < F) {
        g_sum1[t] = 0.f; g_sq1[t] = 0.f;
        g_sum2[t] = 0.f; g_sq2[t] = 0.f;
    }
    if (t < NUM_GRAPHS) g_counts[t] = 0.f;
    for (int i = t; i < NUM_GRAPHS * F; i += blockDim.x * gridDim.x)
        g_pooled[i] = 0.f;
}

// ---------------- bf16 split helpers -------------------------------------------
__device__ __forceinline__ uint32_t pk2(__nv_bfloat16 a, __nv_bfloat16 b) {
    // low 16 bits = a (first / lower-k element), high = b
    return (uint32_t)__bfloat16_as_ushort(b) << 16 | (uint32_t)__bfloat16_as_ushort(a);
}
__device__ __forceinline__ void split_pair(float x, float y,
                                           uint32_t& hi, uint32_t& lo) {
    __nv_bfloat16 hx = __float2bfloat16_rn(x);
    __nv_bfloat16 hy = __float2bfloat16_rn(y);
    float rx = x - __bfloat162float(hx);
    float ry = y - __bfloat162float(hy);
    hi = pk2(hx, hy);
    lo = pk2(__float2bfloat16_rn(rx), __float2bfloat16_rn(ry));
}

// ---------------- prep: pack W [128k x 128n] fp32 into mma B-fragment tables ----
// table index = ((kt*16 + nt)*2 + r)*32 + lane ; element (k,n):
//   k = kt*16 + (lane&3)*2 + r*8 (+1 for high half of the packed reg)
//   n = nt*8 + lane>>2
__global__ void prep_w_kernel(const float* __restrict__ W,
                              uint32_t* __restrict__ tabH,
                              uint32_t* __restrict__ tabL) {
    int tid = blockIdx.x * blockDim.x + threadIdx.x;   // 0..8191
    if (tid >= 8192) return;
    int lane = tid & 31;
    int r    = (tid >> 5) & 1;
    int nt   = (tid >> 6) & 15;
    int kt   = tid >> 10;
    int k = kt * 16 + (lane & 3) * 2 + r * 8;
    int n = nt * 8 + (lane >> 2);
    float v0 = W[k * 128 + n];
    float v1 = W[(k + 1) * 128 + n];
    uint32_t hi, lo;
    split_pair(v0, v1, hi, lo);
    tabH[tid] = hi;
    tabL[tid] = lo;
}

// ---------------- mma wrapper ---------------------------------------------------
__device__ __forceinline__ void mma_bf16(float c[4],
                                         uint32_t a0, uint32_t a1, uint32_t a2, uint32_t a3,
                                         uint32_t b0, uint32_t b1) {
    asm volatile(
        "mma.sync.aligned.m16n8k16.row.col.f32.bf16.bf16.f32 "
        "{%0,%1,%2,%3}, {%4,%5,%6,%7}, {%8,%9}, {%0,%1,%2,%3};"
        : "+f"(c[0]), "+f"(c[1]), "+f"(c[2]), "+f"(c[3])
        : "r"(a0), "r"(a1), "r"(a2), "r"(a3), "r"(b0), "r"(b1));
}

// ---------------- fused MLP: C = relu(A@W1 + b1) @ W2 + b2 ----------------------
// BM=128 rows/block, 256 threads (8 warps), warp w owns rows [w*16, w*16+16).
// Tensor-core bf16 with hi/lo split (3 mma per logical mma). Fully warp-local:
// staging, GEMM1, t1 rewrite, GEMM2 all touch only the warp's own 16 rows.
#define SA 68   // smem row stride in 32-bit words (136 bf16, padded vs 64)
__global__ void __launch_bounds__(256, 2)
mlp_kernel(const float* __restrict__ A, float* __restrict__ C,
           const uint32_t* __restrict__ t1h, const uint32_t* __restrict__ t1l,
           const uint32_t* __restrict__ t2h, const uint32_t* __restrict__ t2l,
           const float* __restrict__ bias1, const float* __restrict__ bias2,
           int M) {
    extern __shared__ uint32_t sm[];
    uint32_t* Ahi = sm;                 // 128 * 68 words
    uint32_t* Alo = sm + 128 * SA;

    const int t    = threadIdx.x;
    const int lane = t & 31;
    const int w    = t >> 5;
    const int base = blockIdx.x * 128;

    // ---- stage A tile: fp32 gmem -> bf16 hi/lo smem (warp-local rows) ----
    {
        int r    = t >> 1;            // row 0..127  (warp w stages rows 16w..16w+15)
        int half = t & 1;             // 64-col half
        int grow = base + r;
        const float4* src = (grow < M)
            ? reinterpret_cast<const float4*>(A + (size_t)grow * 128 + half * 64)
            : nullptr;
        uint32_t* dh = Ahi + r * SA + half * 32;
        uint32_t* dl = Alo + r * SA + half * 32;
#pragma unroll
        for (int i = 0; i < 16; i++) {
            float4 v = src ? src[i] : make_float4(0.f, 0.f, 0.f, 0.f);
            uint32_t h0, l0, h1, l1;
            split_pair(v.x, v.y, h0, l0);
            split_pair(v.z, v.w, h1, l1);
            dh[i * 2]     = h0;  dl[i * 2]     = l0;
            dh[i * 2 + 1] = h1;  dl[i * 2 + 1] = l1;
        }
    }
    __syncwarp();

    const int m0   = w * 16;
    const int arow = m0 + (lane >> 2);
    const int acp  = lane & 3;            // col-pair offset within k-tile

    float acc[16][4];
#pragma unroll
    for (int nt = 0; nt < 16; nt++)
#pragma unroll
        for (int i = 0; i < 4; i++) acc[nt][i] = 0.f;

    // ================= GEMM 1 : A @ W1 =================
#pragma unroll
    for (int kt = 0; kt < 8; kt++) {
        int wp = arow * SA + kt * 8 + acp;
        uint32_t ah0 = Ahi[wp],            ah1 = Ahi[wp + 8 * SA];
        uint32_t ah2 = Ahi[wp + 4],        ah3 = Ahi[wp + 8 * SA + 4];
        uint32_t al0 = Alo[wp],            al1 = Alo[wp + 8 * SA];
        uint32_t al2 = Alo[wp + 4],        al3 = Alo[wp + 8 * SA + 4];
#pragma unroll
        for (int nt = 0; nt < 16; nt++) {
            int bi = (kt * 16 + nt) * 64 + lane;
            uint32_t bh0 = t1h[bi], bh1 = t1h[bi + 32];
            uint32_t bl0 = t1l[bi], bl1 = t1l[bi + 32];
            mma_bf16(acc[nt], ah0, ah1, ah2, ah3, bh0, bh1);
            mma_bf16(acc[nt], ah0, ah1, ah2, ah3, bl0, bl1);
            mma_bf16(acc[nt], al0, al1, al2, al3, bh0, bh1);
        }
    }
    __syncwarp();

    // ---- mid epilogue: bias1 + relu, re-split t1 into the same smem tile ----
#pragma unroll
    for (int nt = 0; nt < 16; nt++) {
        int n0 = nt * 8 + (lane & 3) * 2;
        float bb0 = bias1[n0], bb1 = bias1[n0 + 1];
        float v0 = fmaxf(acc[nt][0] + bb0, 0.f);
        float v1 = fmaxf(acc[nt][1] + bb1, 0.f);
        float v2 = fmaxf(acc[nt][2] + bb0, 0.f);
        float v3 = fmaxf(acc[nt][3] + bb1, 0.f);
        int word = (m0 + (lane >> 2)) * SA + nt * 4 + (lane & 3);
        uint32_t h, l;
        split_pair(v0, v1, h, l);
        Ahi[word] = h;  Alo[word] = l;
        split_pair(v2, v3, h, l);
        Ahi[word + 8 * SA] = h;  Alo[word + 8 * SA] = l;
#pragma unroll
        for (int i = 0; i < 4; i++) acc[nt][i] = 0.f;
    }
    __syncwarp();

    // ================= GEMM 2 : t1 @ W2 =================
#pragma unroll
    for (int kt = 0; kt < 8; kt++) {
        int wp = arow * SA + kt * 8 + acp;
        uint32_t ah0 = Ahi[wp],            ah1 = Ahi[wp + 8 * SA];
        uint32_t ah2 = Ahi[wp + 4],        ah3 = Ahi[wp + 8 * SA + 4];
        uint32_t al0 = Alo[wp],            al1 = Alo[wp + 8 * SA];
        uint32_t al2 = Alo[wp + 4],        al3 = Alo[wp + 8 * SA + 4];
#pragma unroll
        for (int nt = 0; nt < 16; nt++) {
            int bi = (kt * 16 + nt) * 64 + lane;
            uint32_t bh0 = t2h[bi], bh1 = t2h[bi + 32];
            uint32_t bl0 = t2l[bi], bl1 = t2l[bi + 32];
            mma_bf16(acc[nt], ah0, ah1, ah2, ah3, bh0, bh1);
            mma_bf16(acc[nt], ah0, ah1, ah2, ah3, bl0, bl1);
            mma_bf16(acc[nt], al0, al1, al2, al3, bh0, bh1);
        }
    }

    // ---- final epilogue: bias2, fp32 store ----
    int row0 = base + m0 + (lane >> 2);
#pragma unroll
    for (int nt = 0; nt < 16; nt++) {
        int n0 = nt * 8 + (lane & 3) * 2;
        float bb0 = bias2[n0], bb1 = bias2[n0 + 1];
        if (row0 < M) {
            float2 v = make_float2(acc[nt][0] + bb0, acc[nt][1] + bb1);
            *reinterpret_cast<float2*>(C + (size_t)row0 * 128 + n0) = v;
        }
        if (row0 + 8 < M) {
            float2 v = make_float2(acc[nt][2] + bb0, acc[nt][3] + bb1);
            *reinterpret_cast<float2*>(C + (size_t)(row0 + 8) * 128 + n0) = v;
        }
    }
}
#define MLP_SMEM (2 * 128 * SA * 4)   // 69632 bytes

// ---------------- copy init: agg = x ------------------------------------------
__global__ void copy_kernel(const float* __restrict__ src, float* __restrict__ dst) {
    size_t i = (size_t)blockIdx.x * blockDim.x + threadIdx.x;
    size_t n4 = (size_t)N_NODES * F / 4;
    const float4* s4 = reinterpret_cast<const float4*>(src);
    float4* d4 = reinterpret_cast<float4*>(dst);
    for (; i < n4; i += (size_t)blockDim.x * gridDim.x)
        d4[i] = s4[i];
}

// ---------------- edge scatter-add: agg[dst] += x[src] -------------------------
__global__ void scatter_kernel(const float* __restrict__ X,
                               const int* __restrict__ ei,
                               float* __restrict__ agg) {
    int widx = (int)(((size_t)blockIdx.x * blockDim.x + threadIdx.x) >> 5);
    int lane = threadIdx.x & 31;
    if (widx >= N_EDGES) return;
    int s = ei[widx];
    int d = ei[N_EDGES + widx];
    float4 v = reinterpret_cast<const float4*>(X + (size_t)s * F)[lane];
    atomicAdd(reinterpret_cast<float4*>(agg + (size_t)d * F) + lane, v);
}

// ---------------- BN statistics: per-column sum and sum-of-squares -------------
__global__ void bn_stats_kernel(const float* __restrict__ H,
                                float* __restrict__ sum, float* __restrict__ sq) {
    int c = threadIdx.x;   // blockDim = 128
    float s = 0.f, q = 0.f;
    for (int r = blockIdx.x; r < N_NODES; r += gridDim.x) {
        float v = H[(size_t)r * F + c];
        s += v;
        q += v * v;
    }
    atomicAdd(&sum[c], s);
    atomicAdd(&sq[c], q);
}

// ---------------- BN apply + ReLU, writing TWO outputs (h_norm and agg init) ---
__global__ void bn_apply_dual_kernel(const float* __restrict__ H,
                                     const float* __restrict__ sum,
                                     const float* __restrict__ sq,
                                     const float* __restrict__ gamma,
                                     const float* __restrict__ beta,
                                     float* __restrict__ Hn,
                                     float* __restrict__ Agg) {
    size_t idx0 = (size_t)blockIdx.x * blockDim.x + threadIdx.x;
    int c = (int)(idx0 & 127);
    const float invN = 1.0f / (float)N_NODES;
    float mean  = sum[c] * invN;
    float var   = fmaxf(sq[c] * invN - mean * mean, 0.f);
    float scale = gamma[c] * rsqrtf(var + BN_EPS);
    float shift = beta[c] - mean * scale;
    size_t total  = (size_t)N_NODES * F;
    size_t stride = (size_t)blockDim.x * gridDim.x;
    for (size_t i = idx0; i < total; i += stride) {
        float v = fmaxf(H[i] * scale + shift, 0.f);
        Hn[i]  = v;
        Agg[i] = v;
    }
}

// ---------------- per-graph node counts ----------------------------------------
__global__ void count_kernel(const int* __restrict__ batch) {
    int i = blockIdx.x * blockDim.x + threadIdx.x;
    if (i < N_NODES) atomicAdd(&g_counts[batch[i]], 1.0f);
}

// ---------------- fused BN2 + ReLU + segmented pool (batch sorted) -------------
#define POOL_CHUNK 512
__global__ void pool_kernel(const float* __restrict__ H,
                            const float* __restrict__ sum,
                            const float* __restrict__ sq,
                            const float* __restrict__ gamma,
                            const float* __restrict__ beta,
                            const int* __restrict__ batch) {
    const int c = threadIdx.x;   // blockDim = 128
    const float invN = 1.0f / (float)N_NODES;
    float mean  = sum[c] * invN;
    float var   = fmaxf(sq[c] * invN - mean * mean, 0.f);
    float scale = gamma[c] * rsqrtf(var + BN_EPS);
    float shift = beta[c] - mean * scale;

    int r0 = blockIdx.x * POOL_CHUNK;
    if (r0 >= N_NODES) return;
    int r1 = min(r0 + POOL_CHUNK, N_NODES);

    int g = batch[r0];
    float acc = 0.f;
    for (int r = r0; r < r1; r++) {
        int gg = batch[r];
        if (gg != g) {
            atomicAdd(&g_pooled[g * F + c], acc);
            acc = 0.f;
            g = gg;
        }
        float v = fmaxf(H[(size_t)r * F + c] * scale + shift, 0.f);
        acc += v;
    }
    atomicAdd(&g_pooled[g * F + c], acc);
}

// ---------------- head: mean-pool divide + linear + log_softmax ----------------
__global__ void head_kernel(const float* __restrict__ Wlin,
                            const float* __restrict__ blin,
                            float* __restrict__ out) {
    __shared__ float Ws[F * NUM_CLASSES];
    int t = threadIdx.x;   // blockDim = 128, one thread per graph
    for (int i = t; i < F * NUM_CLASSES; i += 128) Ws[i] = Wlin[i];
    __syncthreads();

    int g = t;
    float inv = 1.0f / fmaxf(g_counts[g], 1.0f);
    float logit[NUM_CLASSES];
#pragma unroll
    for (int j = 0; j < NUM_CLASSES; j++) logit[j] = blin[j];
    for (int c = 0; c < F; c++) {
        float p = g_pooled[g * F + c] * inv;
#pragma unroll
        for (int j = 0; j < NUM_CLASSES; j++)
            logit[j] += p * Ws[c * NUM_CLASSES + j];
    }
    float m = logit[0];
#pragma unroll
    for (int j = 1; j < NUM_CLASSES; j++) m = fmaxf(m, logit[j]);
    float se = 0.f;
#pragma unroll
    for (int j = 0; j < NUM_CLASSES; j++) se += expf(logit[j] - m);
    float lse = logf(se);
#pragma unroll
    for (int j = 0; j < NUM_CLASSES; j++)
        out[g * NUM_CLASSES + j] = logit[j] - m - lse;
}

// ================================================================================
extern "C" void kernel_launch(void* const* d_in, const int* in_sizes, int n_in,
                              void* d_out, int out_size) {
    const float* x     = (const float*)d_in[0];
    const int*   ei    = (const int*)d_in[1];
    const int*   batch = (const int*)d_in[2];
    const float* W1a = (const float*)d_in[3];
    const float* b1a = (const float*)d_in[4];
    const float* W1b = (const float*)d_in[5];
    const float* b1b = (const float*)d_in[6];
    const float* gamma1 = (const float*)d_in[7];
    const float* beta1  = (const float*)d_in[8];
    const float* W2a = (const float*)d_in[9];
    const float* b2a = (const float*)d_in[10];
    const float* W2b = (const float*)d_in[11];
    const float* b2b = (const float*)d_in[12];
    const float* gamma2 = (const float*)d_in[13];
    const float* beta2  = (const float*)d_in[14];
    const float* Wlin = (const float*)d_in[15];
    const float* blin = (const float*)d_in[16];
    float* out = (float*)d_out;

    float *pA, *pB, *pC, *pSum1, *pSq1, *pSum2, *pSq2;
    uint32_t *pWH, *pWL;
    cudaGetSymbolAddress((void**)&pA, g_bufA);
    cudaGetSymbolAddress((void**)&pB, g_bufB);
    cudaGetSymbolAddress((void**)&pC, g_bufC);
    cudaGetSymbolAddress((void**)&pSum1, g_sum1);
    cudaGetSymbolAddress((void**)&pSq1,  g_sq1);
    cudaGetSymbolAddress((void**)&pSum2, g_sum2);
    cudaGetSymbolAddress((void**)&pSq2,  g_sq2);
    cudaGetSymbolAddress((void**)&pWH, g_wtabH);
    cudaGetSymbolAddress((void**)&pWL, g_wtabL);

    static int smem_set = 0;
    if (!smem_set) {
        cudaFuncSetAttribute(mlp_kernel,
                             cudaFuncAttributeMaxDynamicSharedMemorySize, MLP_SMEM);
        smem_set = 1;
    }

    const int M = N_NODES;
    const int mlpBlocks = (M + 127) / 128;
    const int scatterBlocks = (N_EDGES * 32) / 256;

    // zero small accumulators + prep weight fragment tables
    zero_small_kernel<<<64, 256>>>();
    prep_w_kernel<<<32, 256>>>(W1a, pWH + 0 * 8192, pWL + 0 * 8192);
    prep_w_kernel<<<32, 256>>>(W1b, pWH + 1 * 8192, pWL + 1 * 8192);
    prep_w_kernel<<<32, 256>>>(W2a, pWH + 2 * 8192, pWL + 2 * 8192);
    prep_w_kernel<<<32, 256>>>(W2b, pWH + 3 * 8192, pWL + 3 * 8192);

    // ---- layer 1: agg1 = x + scatter(x) -> bufA
    copy_kernel<<<4096, 256>>>(x, pA);
    scatter_kernel<<<scatterBlocks, 256>>>(x, ei, pA);
    // fused MLP1 (in-place): h1 = relu(agg1@W1a+b1a)@W1b + b1b -> bufA
    mlp_kernel<<<mlpBlocks, 256, MLP_SMEM>>>(pA, pA,
        pWH + 0 * 8192, pWL + 0 * 8192, pWH + 1 * 8192, pWL + 1 * 8192,
        b1a, b1b, M);
    // BN1 stats + apply
    bn_stats_kernel<<<1024, 128>>>(pA, pSum1, pSq1);
    bn_apply_dual_kernel<<<4096, 256>>>(pA, pSum1, pSq1, gamma1, beta1, pB, pC);

    // ---- layer 2: agg2 = h1n + scatter(h1n) -> bufC
    scatter_kernel<<<scatterBlocks, 256>>>(pB, ei, pC);
    // fused MLP2: h2 -> bufB
    mlp_kernel<<<mlpBlocks, 256, MLP_SMEM>>>(pC, pB,
        pWH + 2 * 8192, pWL + 2 * 8192, pWH + 3 * 8192, pWL + 3 * 8192,
        b2a, b2b, M);
    // BN2 stats on bufB
    bn_stats_kernel<<<1024, 128>>>(pB, pSum2, pSq2);

    // ---- pooling + head
    count_kernel<<<(N_NODES + 255) / 256, 256>>>(batch);
    pool_kernel<<<(N_NODES + POOL_CHUNK - 1) / POOL_CHUNK, 128>>>(
        pB, pSum2, pSq2, gamma2, beta2, batch);
    head_kernel<<<1, 128>>>(Wlin, blin, out);
}